// round 7
// baseline (speedup 1.0000x reference)
#include <cuda_runtime.h>
#include <cuda_fp16.h>
#include <cuda_fp8.h>
#include <cuda_bf16.h>

#define NODE_SIZE 100000
#define DIM 128

// Scratch tables (__device__ globals are the sanctioned scratch):
//   g_zA[n,d] = e4m3( z[n,d] * 2^8 )
//   g_zB[n,d] = e4m3( z[n,d] * w3b[d] * 2^12 )
//   g_P[n]    = sum_d relu(z[n,d]) * v[d]        (fp32, exact)
//   g_Q[n]    = sum_d relu(z[n,d]) * v[128+d]
// logit(i,j) = P[i] + Q[j] + 2^-20 * dot(A[i], B[j])
__device__ unsigned char g_zA[NODE_SIZE * DIM];
__device__ unsigned char g_zB[NODE_SIZE * DIM];
__device__ float g_P[NODE_SIZE];
__device__ float g_Q[NODE_SIZE];
__device__ float g_v[256];   // v[k] = sum_d W2[k,d]*W3[d]

// ---- fold: 256 warps, one per g_v entry ----
__global__ __launch_bounds__(256) void fold_kernel(const float* __restrict__ W2,
                                                   const float* __restrict__ W3) {
    const int tid  = blockIdx.x * blockDim.x + threadIdx.x;
    const int warp = tid >> 5;
    const int lane = tid & 31;
    if (warp < 256) {
        float4 r = __ldg(reinterpret_cast<const float4*>(W2 + warp * 128) + lane);
        float4 t = __ldg(reinterpret_cast<const float4*>(W3) + lane);
        float s = r.x * t.x;
        s = fmaf(r.y, t.y, s);
        s = fmaf(r.z, t.z, s);
        s = fmaf(r.w, t.w, s);
        #pragma unroll
        for (int off = 16; off; off >>= 1)
            s += __shfl_xor_sync(0xFFFFFFFFu, s, off);
        if (lane == 0) g_v[warp] = s;
    }
}

__device__ __forceinline__ unsigned pack_fp8x4(float x, float y, float z, float w) {
    unsigned short lo = __nv_cvt_float2_to_fp8x2(make_float2(x, y), __NV_SATFINITE, __NV_E4M3);
    unsigned short hi = __nv_cvt_float2_to_fp8x2(make_float2(z, w), __NV_SATFINITE, __NV_E4M3);
    return (unsigned)lo | ((unsigned)hi << 16);
}

// ---- convert: one warp per node row; builds A, B, P, Q ----
__global__ __launch_bounds__(256) void convert_kernel(const float* __restrict__ z,
                                                      const float* __restrict__ W3) {
    const int tid    = blockIdx.x * blockDim.x + threadIdx.x;
    const int warp   = tid >> 5;
    const int lane   = tid & 31;
    const int nwarps = (gridDim.x * blockDim.x) >> 5;

    const float4 v1 = *reinterpret_cast<const float4*>(&g_v[lane * 4]);
    const float4 v2 = *reinterpret_cast<const float4*>(&g_v[128 + lane * 4]);
    float4 w3 = __ldg(reinterpret_cast<const float4*>(W3 + 128) + lane);
    w3.x *= 4096.f; w3.y *= 4096.f; w3.z *= 4096.f; w3.w *= 4096.f;  // 2^12 folded

    const float4* __restrict__ zrow = reinterpret_cast<const float4*>(z);
    unsigned* __restrict__ A = reinterpret_cast<unsigned*>(g_zA);
    unsigned* __restrict__ B = reinterpret_cast<unsigned*>(g_zB);

    for (int n = warp; n < NODE_SIZE; n += nwarps) {
        float4 f = __ldg(zrow + (size_t)n * 32 + lane);

        A[n * 32 + lane] = pack_fp8x4(f.x * 256.f, f.y * 256.f,
                                      f.z * 256.f, f.w * 256.f);
        B[n * 32 + lane] = pack_fp8x4(f.x * w3.x, f.y * w3.y,
                                      f.z * w3.z, f.w * w3.w);

        float p = fmaxf(f.x, 0.f) * v1.x;
        p = fmaf(fmaxf(f.y, 0.f), v1.y, p);
        p = fmaf(fmaxf(f.z, 0.f), v1.z, p);
        p = fmaf(fmaxf(f.w, 0.f), v1.w, p);
        float q = fmaxf(f.x, 0.f) * v2.x;
        q = fmaf(fmaxf(f.y, 0.f), v2.y, q);
        q = fmaf(fmaxf(f.z, 0.f), v2.z, q);
        q = fmaf(fmaxf(f.w, 0.f), v2.w, q);

        // paired reduce: 6 SHFL for both sums; P at lane0, Q at lane16
        p += __shfl_xor_sync(0xFFFFFFFFu, p, 16);
        q += __shfl_xor_sync(0xFFFFFFFFu, q, 16);
        float c = (lane & 16) ? q : p;
        c += __shfl_xor_sync(0xFFFFFFFFu, c, 8);
        c += __shfl_xor_sync(0xFFFFFFFFu, c, 4);
        c += __shfl_xor_sync(0xFFFFFFFFu, c, 2);
        c += __shfl_xor_sync(0xFFFFFFFFu, c, 1);
        if (lane == 0)  g_P[n] = c;
        if (lane == 16) g_Q[n] = c;
    }
}

// ---- main kernel ----
__device__ __forceinline__ __half2 fp8x2_to_half2(unsigned short v) {
    __half2_raw hr = __nv_cvt_fp8x2_to_halfraw2((__nv_fp8x2_storage_t)v, __NV_E4M3);
    return *reinterpret_cast<__half2*>(&hr);
}

__device__ __forceinline__ float dot8(unsigned ua, unsigned ub) {
    __half2 a0 = fp8x2_to_half2((unsigned short)(ua & 0xFFFF));
    __half2 a1 = fp8x2_to_half2((unsigned short)(ua >> 16));
    __half2 b0 = fp8x2_to_half2((unsigned short)(ub & 0xFFFF));
    __half2 b1 = fp8x2_to_half2((unsigned short)(ub >> 16));
    __half2 acc = __hmul2(a0, b0);
    acc = __hfma2(a1, b1, acc);
    float2 f = __half22float2(acc);
    return f.x + f.y;
}

// Reduce 4 warp-wide accumulators with 9 SHFL + 3 SEL.
// Result: lane0 -> sum(s0), lane16 -> sum(s1), lane8 -> sum(s2), lane24 -> sum(s3).
__device__ __forceinline__ float reduce4(float s0, float s1, float s2, float s3,
                                         int lane) {
    s0 += __shfl_xor_sync(0xFFFFFFFFu, s0, 16);
    s1 += __shfl_xor_sync(0xFFFFFFFFu, s1, 16);
    s2 += __shfl_xor_sync(0xFFFFFFFFu, s2, 16);
    s3 += __shfl_xor_sync(0xFFFFFFFFu, s3, 16);
    float c01 = (lane & 16) ? s1 : s0;
    float c23 = (lane & 16) ? s3 : s2;
    c01 += __shfl_xor_sync(0xFFFFFFFFu, c01, 8);
    c23 += __shfl_xor_sync(0xFFFFFFFFu, c23, 8);
    float d = (lane & 8) ? c23 : c01;
    d += __shfl_xor_sync(0xFFFFFFFFu, d, 4);
    d += __shfl_xor_sync(0xFFFFFFFFu, d, 2);
    d += __shfl_xor_sync(0xFFFFFFFFu, d, 1);
    return d;
}

__global__ __launch_bounds__(256, 3) void neumf_kernel(
    const int* __restrict__ e_true,
    const int* __restrict__ e_false,
    float* __restrict__ out,
    int E_true, int E_total)
{
    const int lane   = threadIdx.x & 31;
    const int warp   = (blockIdx.x * blockDim.x + threadIdx.x) >> 5;
    const int nwarps = (gridDim.x * blockDim.x) >> 5;

    const unsigned* __restrict__ za = reinterpret_cast<const unsigned*>(g_zA);
    const unsigned* __restrict__ zb = reinterpret_cast<const unsigned*>(g_zB);

    int e = warp * 8;
    const int stride = nwarps * 8;

    for (; e + 7 < E_total; e += stride) {
        // --- indices: 4 uniform int4 loads when group doesn't straddle ---
        int2 id[8];
        if (e + 8 <= E_true) {
            const int4* p = reinterpret_cast<const int4*>(e_true + 2 * e);
            int4 q0 = __ldg(p + 0), q1 = __ldg(p + 1);
            int4 q2 = __ldg(p + 2), q3 = __ldg(p + 3);
            id[0] = make_int2(q0.x, q0.y); id[1] = make_int2(q0.z, q0.w);
            id[2] = make_int2(q1.x, q1.y); id[3] = make_int2(q1.z, q1.w);
            id[4] = make_int2(q2.x, q2.y); id[5] = make_int2(q2.z, q2.w);
            id[6] = make_int2(q3.x, q3.y); id[7] = make_int2(q3.z, q3.w);
        } else if (e >= E_true) {
            const int4* p = reinterpret_cast<const int4*>(e_false + 2 * (e - E_true));
            int4 q0 = __ldg(p + 0), q1 = __ldg(p + 1);
            int4 q2 = __ldg(p + 2), q3 = __ldg(p + 3);
            id[0] = make_int2(q0.x, q0.y); id[1] = make_int2(q0.z, q0.w);
            id[2] = make_int2(q1.x, q1.y); id[3] = make_int2(q1.z, q1.w);
            id[4] = make_int2(q2.x, q2.y); id[5] = make_int2(q2.z, q2.w);
            id[6] = make_int2(q3.x, q3.y); id[7] = make_int2(q3.z, q3.w);
        } else {
            #pragma unroll
            for (int k = 0; k < 8; ++k) {
                int ek = e + k;
                id[k] = __ldg(reinterpret_cast<const int2*>(
                    ek < E_true ? e_true + 2 * ek
                                : e_false + 2 * (ek - E_true)));
            }
        }

        // --- 16 row gathers + 16 scalar gathers, all issued up front ---
        unsigned a[8], b[8];
        #pragma unroll
        for (int k = 0; k < 8; ++k) {
            a[k] = __ldg(za + (((size_t)id[k].x << 5) + lane));
            b[k] = __ldg(zb + (((size_t)id[k].y << 5) + lane));
        }
        float pq[8];
        #pragma unroll
        for (int k = 0; k < 8; ++k)
            pq[k] = __ldg(g_P + id[k].x) + __ldg(g_Q + id[k].y);

        float s[8];
        #pragma unroll
        for (int k = 0; k < 8; ++k) {
            s[k] = dot8(a[k], b[k]);
            if (lane == 0) s[k] = fmaf(pq[k], 0x1p20f, s[k]);  // fold P+Q pre-reduce
        }

        float d0 = reduce4(s[0], s[1], s[2], s[3], lane);
        float d1 = reduce4(s[4], s[5], s[6], s[7], lane);

        if ((lane & 7) == 0) {
            int off = ((lane >> 3) & 1) * 2 + (lane >> 4);  // 0->0, 8->2, 16->1, 24->3
            out[e + off]     = 1.f / (1.f + __expf(-d0 * 0x1p-20f));
            out[e + 4 + off] = 1.f / (1.f + __expf(-d1 * 0x1p-20f));
        }
    }

    // Tail
    for (; e < E_total; ++e) {
        int2 i0 = __ldg(reinterpret_cast<const int2*>(
             e < E_true ? e_true + 2 * e : e_false + 2 * (e - E_true)));
        const unsigned aa = __ldg(za + (((size_t)i0.x << 5) + lane));
        const unsigned bb = __ldg(zb + (((size_t)i0.y << 5) + lane));
        float pq = __ldg(g_P + i0.x) + __ldg(g_Q + i0.y);
        float s = dot8(aa, bb);
        if (lane == 0) s = fmaf(pq, 0x1p20f, s);
        #pragma unroll
        for (int off = 16; off; off >>= 1)
            s += __shfl_xor_sync(0xFFFFFFFFu, s, off);
        if (lane == 0)
            out[e] = 1.f / (1.f + __expf(-s * 0x1p-20f));
    }
}

extern "C" void kernel_launch(void* const* d_in, const int* in_sizes, int n_in,
                              void* d_out, int out_size) {
    // metadata order: X, train_edges, train_false_edges, z, weight_two, weight_three
    const int*   e_true  = (const int*)  d_in[1];
    const int*   e_false = (const int*)  d_in[2];
    const float* z       = (const float*)d_in[3];
    const float* W2      = (const float*)d_in[4];
    const float* W3      = (const float*)d_in[5];
    float* out = (float*)d_out;

    const int E_true  = in_sizes[1] / 2;
    const int E_total = E_true + in_sizes[2] / 2;

    int sm_count = 148;
    cudaDeviceGetAttribute(&sm_count, cudaDevAttrMultiProcessorCount, 0);

    fold_kernel<<<32, 256>>>(W2, W3);               // g_v (256 warps)
    convert_kernel<<<sm_count * 8, 256>>>(z, W3);   // A, B, P, Q

    int blocks_per_sm = 3;
    cudaOccupancyMaxActiveBlocksPerMultiprocessor(&blocks_per_sm, neumf_kernel, 256, 0);
    if (blocks_per_sm < 1) blocks_per_sm = 1;

    neumf_kernel<<<sm_count * blocks_per_sm, 256>>>(e_true, e_false, out,
                                                    E_true, E_total);
}

// round 8
// speedup vs baseline: 1.1322x; 1.1322x over previous
#include <cuda_runtime.h>
#include <cuda_fp16.h>
#include <cuda_fp8.h>
#include <cuda_bf16.h>

#define NODE_SIZE 100000
#define DIM 128

// Scratch (__device__ globals are the sanctioned scratch):
//   g_zA[n,d] = e4m3( z[n,d] * 2^8 )
//   g_P[n]    = sum_d relu(z[n,d]) * v[d]        (fp32, exact)
//   g_Q[n]    = sum_d relu(z[n,d]) * v[128+d]
//   g_v[k]    = sum_d W2[k,d]*W3[d]
// logit(i,j) = P[i] + Q[j] + 2^-20 * dot_d( A[i,d], A[j,d] * (w3b[d]*2^4) )
__device__ unsigned char g_zA[NODE_SIZE * DIM];
__device__ float g_P[NODE_SIZE];
__device__ float g_Q[NODE_SIZE];
__device__ float g_v[256];

// ---- fold: 256 one-warp blocks, one per g_v entry (spreads cold W2 fetch) ----
__global__ __launch_bounds__(128) void fold_kernel(const float* __restrict__ W2,
                                                   const float* __restrict__ W3) {
    const int warp = (blockIdx.x * blockDim.x + threadIdx.x) >> 5;
    const int lane = threadIdx.x & 31;
    if (warp < 256) {
        float4 r = __ldg(reinterpret_cast<const float4*>(W2 + warp * 128) + lane);
        float4 t = __ldg(reinterpret_cast<const float4*>(W3) + lane);
        float s = r.x * t.x;
        s = fmaf(r.y, t.y, s);
        s = fmaf(r.z, t.z, s);
        s = fmaf(r.w, t.w, s);
        #pragma unroll
        for (int off = 16; off; off >>= 1)
            s += __shfl_xor_sync(0xFFFFFFFFu, s, off);
        if (lane == 0) g_v[warp] = s;
    }
}

__device__ __forceinline__ unsigned pack_fp8x4(float x, float y, float z, float w) {
    unsigned short lo = __nv_cvt_float2_to_fp8x2(make_float2(x, y), __NV_SATFINITE, __NV_E4M3);
    unsigned short hi = __nv_cvt_float2_to_fp8x2(make_float2(z, w), __NV_SATFINITE, __NV_E4M3);
    return (unsigned)lo | ((unsigned)hi << 16);
}

// ---- convert: one warp per node row; builds A, P, Q ----
__global__ __launch_bounds__(256) void convert_kernel(const float* __restrict__ z) {
    const int tid    = blockIdx.x * blockDim.x + threadIdx.x;
    const int warp   = tid >> 5;
    const int lane   = tid & 31;
    const int nwarps = (gridDim.x * blockDim.x) >> 5;

    const float4 v1 = *reinterpret_cast<const float4*>(&g_v[lane * 4]);
    const float4 v2 = *reinterpret_cast<const float4*>(&g_v[128 + lane * 4]);

    const float4* __restrict__ zrow = reinterpret_cast<const float4*>(z);
    unsigned* __restrict__ A = reinterpret_cast<unsigned*>(g_zA);

    for (int n = warp; n < NODE_SIZE; n += nwarps) {
        float4 f = __ldg(zrow + (size_t)n * 32 + lane);

        A[n * 32 + lane] = pack_fp8x4(f.x * 256.f, f.y * 256.f,
                                      f.z * 256.f, f.w * 256.f);

        float p = fmaxf(f.x, 0.f) * v1.x;
        p = fmaf(fmaxf(f.y, 0.f), v1.y, p);
        p = fmaf(fmaxf(f.z, 0.f), v1.z, p);
        p = fmaf(fmaxf(f.w, 0.f), v1.w, p);
        float q = fmaxf(f.x, 0.f) * v2.x;
        q = fmaf(fmaxf(f.y, 0.f), v2.y, q);
        q = fmaf(fmaxf(f.z, 0.f), v2.z, q);
        q = fmaf(fmaxf(f.w, 0.f), v2.w, q);

        // paired reduce: 6 SHFL for both sums; P at lane0, Q at lane16
        p += __shfl_xor_sync(0xFFFFFFFFu, p, 16);
        q += __shfl_xor_sync(0xFFFFFFFFu, q, 16);
        float c = (lane & 16) ? q : p;
        c += __shfl_xor_sync(0xFFFFFFFFu, c, 8);
        c += __shfl_xor_sync(0xFFFFFFFFu, c, 4);
        c += __shfl_xor_sync(0xFFFFFFFFu, c, 2);
        c += __shfl_xor_sync(0xFFFFFFFFu, c, 1);
        if (lane == 0)  g_P[n] = c;
        if (lane == 16) g_Q[n] = c;
    }
}

// ---- main kernel ----
__device__ __forceinline__ __half2 fp8x2_to_half2(unsigned short v) {
    __half2_raw hr = __nv_cvt_fp8x2_to_halfraw2((__nv_fp8x2_storage_t)v, __NV_E4M3);
    return *reinterpret_cast<__half2*>(&hr);
}

// dot_d a[d]*b[d]*w[d] over this lane's 4 dims (a,b in 2^8 domain; w in 2^4 domain)
__device__ __forceinline__ float dot8w(unsigned ua, unsigned ub,
                                       __half2 w0, __half2 w1) {
    __half2 a0 = fp8x2_to_half2((unsigned short)(ua & 0xFFFF));
    __half2 a1 = fp8x2_to_half2((unsigned short)(ua >> 16));
    __half2 b0 = fp8x2_to_half2((unsigned short)(ub & 0xFFFF));
    __half2 b1 = fp8x2_to_half2((unsigned short)(ub >> 16));
    __half2 acc = __hmul2(__hmul2(a0, b0), w0);
    acc = __hfma2(__hmul2(a1, b1), w1, acc);
    float2 f = __half22float2(acc);
    return f.x + f.y;
}

// Reduce 4 warp-wide accumulators with 9 SHFL + 3 SEL.
// Result: lane0 -> sum(s0), lane16 -> sum(s1), lane8 -> sum(s2), lane24 -> sum(s3).
__device__ __forceinline__ float reduce4(float s0, float s1, float s2, float s3,
                                         int lane) {
    s0 += __shfl_xor_sync(0xFFFFFFFFu, s0, 16);
    s1 += __shfl_xor_sync(0xFFFFFFFFu, s1, 16);
    s2 += __shfl_xor_sync(0xFFFFFFFFu, s2, 16);
    s3 += __shfl_xor_sync(0xFFFFFFFFu, s3, 16);
    float c01 = (lane & 16) ? s1 : s0;
    float c23 = (lane & 16) ? s3 : s2;
    c01 += __shfl_xor_sync(0xFFFFFFFFu, c01, 8);
    c23 += __shfl_xor_sync(0xFFFFFFFFu, c23, 8);
    float d = (lane & 8) ? c23 : c01;
    d += __shfl_xor_sync(0xFFFFFFFFu, d, 4);
    d += __shfl_xor_sync(0xFFFFFFFFu, d, 2);
    d += __shfl_xor_sync(0xFFFFFFFFu, d, 1);
    return d;
}

__global__ __launch_bounds__(256, 3) void neumf_kernel(
    const int* __restrict__ e_true,
    const int* __restrict__ e_false,
    const float* __restrict__ W3,
    float* __restrict__ out,
    int E_true, int E_total)
{
    const int lane   = threadIdx.x & 31;
    const int warp   = (blockIdx.x * blockDim.x + threadIdx.x) >> 5;
    const int nwarps = (gridDim.x * blockDim.x) >> 5;

    // per-lane w3b * 2^4 as two half2
    float4 wf = __ldg(reinterpret_cast<const float4*>(W3 + 128) + lane);
    const __half2 w0 = __floats2half2_rn(wf.x * 16.f, wf.y * 16.f);
    const __half2 w1 = __floats2half2_rn(wf.z * 16.f, wf.w * 16.f);

    const unsigned* __restrict__ za = reinterpret_cast<const unsigned*>(g_zA);

    int e = warp * 8;
    const int stride = nwarps * 8;

    for (; e + 7 < E_total; e += stride) {
        // --- uniform index loads for row gathers ---
        int2 id[8];
        if (e + 8 <= E_true) {
            const int4* p = reinterpret_cast<const int4*>(e_true + 2 * e);
            int4 q0 = __ldg(p + 0), q1 = __ldg(p + 1);
            int4 q2 = __ldg(p + 2), q3 = __ldg(p + 3);
            id[0] = make_int2(q0.x, q0.y); id[1] = make_int2(q0.z, q0.w);
            id[2] = make_int2(q1.x, q1.y); id[3] = make_int2(q1.z, q1.w);
            id[4] = make_int2(q2.x, q2.y); id[5] = make_int2(q2.z, q2.w);
            id[6] = make_int2(q3.x, q3.y); id[7] = make_int2(q3.z, q3.w);
        } else if (e >= E_true) {
            const int4* p = reinterpret_cast<const int4*>(e_false + 2 * (e - E_true));
            int4 q0 = __ldg(p + 0), q1 = __ldg(p + 1);
            int4 q2 = __ldg(p + 2), q3 = __ldg(p + 3);
            id[0] = make_int2(q0.x, q0.y); id[1] = make_int2(q0.z, q0.w);
            id[2] = make_int2(q1.x, q1.y); id[3] = make_int2(q1.z, q1.w);
            id[4] = make_int2(q2.x, q2.y); id[5] = make_int2(q2.z, q2.w);
            id[6] = make_int2(q3.x, q3.y); id[7] = make_int2(q3.z, q3.w);
        } else {
            #pragma unroll
            for (int k = 0; k < 8; ++k) {
                int ek = e + k;
                id[k] = __ldg(reinterpret_cast<const int2*>(
                    ek < E_true ? e_true + 2 * ek
                                : e_false + 2 * (ek - E_true)));
            }
        }

        // --- lane-distributed P/Q: 2 LDG total for all 8 edges ---
        // lanes 0..7: P[i_k] for k=lane; lanes 8..15: Q[j_k] for k=lane-8
        float pqv = 0.f;
        if (lane < 16) {
            int k  = lane & 7;
            int ek = e + k;
            const int* p = ek < E_true ? e_true + 2 * ek
                                       : e_false + 2 * (ek - E_true);
            int node = __ldg(p + (lane >> 3));          // +0 -> i, +1 -> j
            pqv = __ldg(((lane < 8) ? g_P : g_Q) + node);
        }
        // pq[k] lands in lanes 0..7
        float pqs = pqv + __shfl_xor_sync(0xFFFFFFFFu, pqv, 8);

        // --- 16 row gathers, all issued before any consume ---
        unsigned a[8], b[8];
        #pragma unroll
        for (int k = 0; k < 8; ++k) {
            a[k] = __ldg(za + (((size_t)id[k].x << 5) + lane));
            b[k] = __ldg(za + (((size_t)id[k].y << 5) + lane));
        }

        float s[8];
        #pragma unroll
        for (int k = 0; k < 8; ++k)
            s[k] = dot8w(a[k], b[k], w0, w1);

        float d0 = reduce4(s[0], s[1], s[2], s[3], lane);
        float d1 = reduce4(s[4], s[5], s[6], s[7], lane);

        // route pq to writer lanes, then write
        int off = ((lane >> 3) & 1) * 2 + (lane >> 4);  // 0->0, 8->2, 16->1, 24->3
        float pq0 = __shfl_sync(0xFFFFFFFFu, pqs, off);
        float pq1 = __shfl_sync(0xFFFFFFFFu, pqs, 4 + off);
        if ((lane & 7) == 0) {
            out[e + off]     = 1.f / (1.f + __expf(-(pq0 + d0 * 0x1p-20f)));
            out[e + 4 + off] = 1.f / (1.f + __expf(-(pq1 + d1 * 0x1p-20f)));
        }
    }

    // Tail
    for (; e < E_total; ++e) {
        int2 i0 = __ldg(reinterpret_cast<const int2*>(
             e < E_true ? e_true + 2 * e : e_false + 2 * (e - E_true)));
        const unsigned aa = __ldg(za + (((size_t)i0.x << 5) + lane));
        const unsigned bb = __ldg(za + (((size_t)i0.y << 5) + lane));
        float pq = __ldg(g_P + i0.x) + __ldg(g_Q + i0.y);
        float s = dot8w(aa, bb, w0, w1);
        #pragma unroll
        for (int off = 16; off; off >>= 1)
            s += __shfl_xor_sync(0xFFFFFFFFu, s, off);
        if (lane == 0)
            out[e] = 1.f / (1.f + __expf(-(pq + s * 0x1p-20f)));
    }
}

extern "C" void kernel_launch(void* const* d_in, const int* in_sizes, int n_in,
                              void* d_out, int out_size) {
    // metadata order: X, train_edges, train_false_edges, z, weight_two, weight_three
    const int*   e_true  = (const int*)  d_in[1];
    const int*   e_false = (const int*)  d_in[2];
    const float* z       = (const float*)d_in[3];
    const float* W2      = (const float*)d_in[4];
    const float* W3      = (const float*)d_in[5];
    float* out = (float*)d_out;

    const int E_true  = in_sizes[1] / 2;
    const int E_total = E_true + in_sizes[2] / 2;

    int sm_count = 148;
    cudaDeviceGetAttribute(&sm_count, cudaDevAttrMultiProcessorCount, 0);

    fold_kernel<<<64, 128>>>(W2, W3);           // g_v (256 warps, spread wide)
    convert_kernel<<<sm_count * 8, 256>>>(z);   // A, P, Q

    int blocks_per_sm = 3;
    cudaOccupancyMaxActiveBlocksPerMultiprocessor(&blocks_per_sm, neumf_kernel, 256, 0);
    if (blocks_per_sm < 1) blocks_per_sm = 1;

    neumf_kernel<<<sm_count * blocks_per_sm, 256>>>(e_true, e_false, W3, out,
                                                    E_true, E_total);
}